// round 10
// baseline (speedup 1.0000x reference)
#include <cuda_runtime.h>
#include <cuda_fp16.h>

#define N_   2
#define C_   256
#define H_   200
#define W_   304
#define HW_  (H_ * W_)
#define PH_  7
#define PW_  7
#define NBIN 49
#define NS   196          // 49 bins * 4 samples
#define SCALE 0.25f
#define CH_Q   64               // channels per work item (quarter)
#define GRP    (CH_Q / 4)       // 16 4-channel (uint2) groups
#define NSM    148
#define BPSM   8
#define GATHER_GRID (NSM * BPSM)   // 1184 persistent blocks

// NHWC fp16 scratch (62.3 MB) -> L2-resident on GB300 (126 MB L2).
__device__ __half g_nhwc[(size_t)N_ * HW_ * C_];
// work-stealing queue head (reset by the transpose kernel each launch)
__device__ int g_ctr;

// ---------------------------------------------------------------------------
// Kernel 1: NCHW fp32 -> NHWC fp16. Tile = 128 channels x 32 hw positions.
// Also resets the gather work queue (runs strictly before the gather).
// ---------------------------------------------------------------------------
__global__ void __launch_bounds__(256) nchw_to_nhwc(const float* __restrict__ in) {
    if (blockIdx.x == 0 && blockIdx.y == 0 && blockIdx.z == 0 && threadIdx.x == 0)
        g_ctr = 0;

    __shared__ unsigned int tile[32 * 65];   // [hw][channel-pair], pad 65
    const int n   = blockIdx.z;
    const int hw0 = blockIdx.x * 32;
    const int c0  = blockIdx.y * 128;
    const int t   = threadIdx.x;
    const int w   = t >> 5;     // warp 0..7
    const int l   = t & 31;     // lane = hw offset

    const float* src = in + (size_t)n * C_ * HW_ + (size_t)c0 * HW_ + hw0;
#pragma unroll
    for (int i = 0; i < 8; ++i) {
        const int cp = i * 8 + w;                       // channel pair 0..63
        const float f0 = __ldcs(&src[(size_t)(2 * cp + 0) * HW_ + l]);
        const float f1 = __ldcs(&src[(size_t)(2 * cp + 1) * HW_ + l]);
        const __half2 h = __floats2half2_rn(f0, f1);
        tile[l * 65 + cp] = *reinterpret_cast<const unsigned int*>(&h);
    }
    __syncthreads();

    __half* dst = g_nhwc + (size_t)n * HW_ * C_ + (size_t)hw0 * C_ + c0;
    const int c16 = t & 15;     // 8-channel group (4 uints)
    const int sh  = t >> 4;     // 0..15
#pragma unroll
    for (int pass = 0; pass < 2; ++pass) {
        const int hwr = pass * 16 + sh;
        uint4 v;
        v.x = tile[hwr * 65 + 4 * c16 + 0];
        v.y = tile[hwr * 65 + 4 * c16 + 1];
        v.z = tile[hwr * 65 + 4 * c16 + 2];
        v.w = tile[hwr * 65 + 4 * c16 + 3];
        *reinterpret_cast<uint4*>(dst + (size_t)hwr * C_ + 8 * c16) = v;
    }
}

__device__ __forceinline__ __half2 as_h2(unsigned int v) {
    return *reinterpret_cast<const __half2*>(&v);
}

// ---------------------------------------------------------------------------
// Kernel 2: persistent work-stealing gather. 1184 blocks drain R*4 work items
// (roi, 64-channel quarter) from a global atomic queue -> no wave-quantization
// tail. Per item: 256 threads = 16 channel groups x 16 bin phases; pair-fused
// HFMA2 chains, 0.25 pre-scaled weights, identity [c][s] staging, vector-copy
// output pass.
// ---------------------------------------------------------------------------
__global__ void __launch_bounds__(256, 8) roi_align_rotated(
    const float* __restrict__ rois, float* __restrict__ out, int total_items) {
    extern __shared__ char smem_raw[];
    int*          s_off = (int*)smem_raw;                    // NS*4 ints    (3136 B)
    unsigned int* s_wh  = (unsigned int*)(smem_raw + NS*16); // NS*4 half2   (3136 B)
    float*        s_out = (float*)(smem_raw + NS * 32);      // 64*49 floats (12544 B)
    __shared__ int s_wi;

    const int tid = threadIdx.x;
    const uint2* __restrict__ in2 = (const uint2*)g_nhwc;
    const int cg = tid & (GRP - 1);   // 4-channel group within this quarter
    const int q  = tid >> 4;          // bin phase 0..15

    for (;;) {
        if (tid == 0) s_wi = atomicAdd(&g_ctr, 1);
        __syncthreads();               // publishes s_wi; also separates prior
        const int wi = s_wi;           // output pass from this setup phase
        if (wi >= total_items) return;
        const int r    = wi >> 2;
        const int quad = wi & 3;

        if (tid < NS) {
            const float* rp = rois + (size_t)r * 6;
            const int   b     = (int)rp[0];
            const float cxr   = fmaf(rp[1], SCALE, -0.5f);
            const float cyr   = fmaf(rp[2], SCALE, -0.5f);
            const float rw    = rp[3] * SCALE;
            const float rh    = rp[4] * SCALE;
            const float theta = rp[5] * 0.017453292519943295f;  // pi/180
            float st, ct;
            sincosf(theta, &st, &ct);

            const float bin_h = rh * (1.0f / PH_);
            const float bin_w = rw * (1.0f / PW_);

            // sample id t = (ph*7+pw)*4 + gy*2 + gx
            const int g  = tid & 3;
            const int s  = tid >> 2;
            const int gy = g >> 1;
            const int gx = g & 1;
            const int ph = s / 7;
            const int pw = s - ph * 7;

            const float yy = -0.5f * rh + (float)ph * bin_h + ((float)gy + 0.5f) * bin_h * 0.5f;
            const float xx = -0.5f * rw + (float)pw * bin_w + ((float)gx + 0.5f) * bin_w * 0.5f;

            const float y = yy * ct - xx * st + cyr;
            const float x = yy * st + xx * ct + cxr;

            const bool valid = (y >= -1.0f) && (y <= (float)H_) &&
                               (x >= -1.0f) && (x <= (float)W_);

            const float yc = fminf(fmaxf(y, 0.0f), (float)(H_ - 1));
            const float xc = fminf(fmaxf(x, 0.0f), (float)(W_ - 1));
            const int   yl = (int)floorf(yc);
            const int   xl = (int)floorf(xc);
            const int   yh = min(yl + 1, H_ - 1);
            const int   xh = min(xl + 1, W_ - 1);
            const float ly = yc - (float)yl;
            const float lx = xc - (float)xl;
            const float hy = 1.0f - ly;
            const float hx = 1.0f - lx;
            // 0.25 mean factor pre-folded into fp16 weights (exact: power of 2)
            const float vf = valid ? 0.25f : 0.0f;

            const int base = b * HW_;
            const int hofs = quad * GRP;   // channel-quarter offset, uint2 units
            s_off[tid * 4 + 0] = (base + yl * W_ + xl) * (C_ / 4) + hofs;
            s_off[tid * 4 + 1] = (base + yl * W_ + xh) * (C_ / 4) + hofs;
            s_off[tid * 4 + 2] = (base + yh * W_ + xl) * (C_ / 4) + hofs;
            s_off[tid * 4 + 3] = (base + yh * W_ + xh) * (C_ / 4) + hofs;
            const __half2 w0 = __float2half2_rn(hy * hx * vf);
            const __half2 w1 = __float2half2_rn(hy * lx * vf);
            const __half2 w2 = __float2half2_rn(ly * hx * vf);
            const __half2 w3 = __float2half2_rn(ly * lx * vf);
            s_wh[tid * 4 + 0] = *reinterpret_cast<const unsigned int*>(&w0);
            s_wh[tid * 4 + 1] = *reinterpret_cast<const unsigned int*>(&w1);
            s_wh[tid * 4 + 2] = *reinterpret_cast<const unsigned int*>(&w2);
            s_wh[tid * 4 + 3] = *reinterpret_cast<const unsigned int*>(&w3);
        }
        __syncthreads();

        for (int s = q; s < NBIN; s += 16) {
            const int  t0  = s << 2;
            const int4  oA0 = ((const int4*)s_off)[t0 + 0];
            const int4  oA1 = ((const int4*)s_off)[t0 + 1];
            const int4  oB0 = ((const int4*)s_off)[t0 + 2];
            const int4  oB1 = ((const int4*)s_off)[t0 + 3];
            const uint4 wA0 = ((const uint4*)s_wh)[t0 + 0];
            const uint4 wA1 = ((const uint4*)s_wh)[t0 + 1];
            const uint4 wB0 = ((const uint4*)s_wh)[t0 + 2];
            const uint4 wB1 = ((const uint4*)s_wh)[t0 + 3];

            const uint2 a0 = in2[oA0.x + cg];
            const uint2 a1 = in2[oA0.y + cg];
            const uint2 a2 = in2[oA0.z + cg];
            const uint2 a3 = in2[oA0.w + cg];
            const uint2 a4 = in2[oA1.x + cg];
            const uint2 a5 = in2[oA1.y + cg];
            const uint2 a6 = in2[oA1.z + cg];
            const uint2 a7 = in2[oA1.w + cg];
            const uint2 b0 = in2[oB0.x + cg];
            const uint2 b1 = in2[oB0.y + cg];
            const uint2 b2 = in2[oB0.z + cg];
            const uint2 b3 = in2[oB0.w + cg];
            const uint2 b4 = in2[oB1.x + cg];
            const uint2 b5 = in2[oB1.y + cg];
            const uint2 b6 = in2[oB1.z + cg];
            const uint2 b7 = in2[oB1.w + cg];

            // pair A: fused fp16 chain over 8 corner terms (samples 0,1)
            __half2 h0 = __hmul2(as_h2(a0.x), as_h2(wA0.x));
            __half2 h1 = __hmul2(as_h2(a0.y), as_h2(wA0.x));
            h0 = __hfma2(as_h2(a1.x), as_h2(wA0.y), h0);
            h1 = __hfma2(as_h2(a1.y), as_h2(wA0.y), h1);
            h0 = __hfma2(as_h2(a2.x), as_h2(wA0.z), h0);
            h1 = __hfma2(as_h2(a2.y), as_h2(wA0.z), h1);
            h0 = __hfma2(as_h2(a3.x), as_h2(wA0.w), h0);
            h1 = __hfma2(as_h2(a3.y), as_h2(wA0.w), h1);
            h0 = __hfma2(as_h2(a4.x), as_h2(wA1.x), h0);
            h1 = __hfma2(as_h2(a4.y), as_h2(wA1.x), h1);
            h0 = __hfma2(as_h2(a5.x), as_h2(wA1.y), h0);
            h1 = __hfma2(as_h2(a5.y), as_h2(wA1.y), h1);
            h0 = __hfma2(as_h2(a6.x), as_h2(wA1.z), h0);
            h1 = __hfma2(as_h2(a6.y), as_h2(wA1.z), h1);
            h0 = __hfma2(as_h2(a7.x), as_h2(wA1.w), h0);
            h1 = __hfma2(as_h2(a7.y), as_h2(wA1.w), h1);
            // pair B: independent chain (samples 2,3)
            __half2 g0 = __hmul2(as_h2(b0.x), as_h2(wB0.x));
            __half2 g1 = __hmul2(as_h2(b0.y), as_h2(wB0.x));
            g0 = __hfma2(as_h2(b1.x), as_h2(wB0.y), g0);
            g1 = __hfma2(as_h2(b1.y), as_h2(wB0.y), g1);
            g0 = __hfma2(as_h2(b2.x), as_h2(wB0.z), g0);
            g1 = __hfma2(as_h2(b2.y), as_h2(wB0.z), g1);
            g0 = __hfma2(as_h2(b3.x), as_h2(wB0.w), g0);
            g1 = __hfma2(as_h2(b3.y), as_h2(wB0.w), g1);
            g0 = __hfma2(as_h2(b4.x), as_h2(wB1.x), g0);
            g1 = __hfma2(as_h2(b4.y), as_h2(wB1.x), g1);
            g0 = __hfma2(as_h2(b5.x), as_h2(wB1.y), g0);
            g1 = __hfma2(as_h2(b5.y), as_h2(wB1.y), g1);
            g0 = __hfma2(as_h2(b6.x), as_h2(wB1.z), g0);
            g1 = __hfma2(as_h2(b6.y), as_h2(wB1.z), g1);
            g0 = __hfma2(as_h2(b7.x), as_h2(wB1.w), g0);
            g1 = __hfma2(as_h2(b7.y), as_h2(wB1.w), g1);

            // combine pairs in fp32 (weights carry the 0.25 mean factor)
            const float2 fA0 = __half22float2(h0);
            const float2 fA1 = __half22float2(h1);
            const float2 fB0 = __half22float2(g0);
            const float2 fB1 = __half22float2(g1);
            // identity staging: s_out[c*49 + s]
            s_out[(4 * cg + 0) * NBIN + s] = fA0.x + fB0.x;
            s_out[(4 * cg + 1) * NBIN + s] = fA0.y + fB0.y;
            s_out[(4 * cg + 2) * NBIN + s] = fA1.x + fB1.x;
            s_out[(4 * cg + 3) * NBIN + s] = fA1.y + fB1.y;
        }
        __syncthreads();

        // output pass: pure vector copy, zero index math
        const float4* __restrict__ s4 = (const float4*)s_out;
        float4* __restrict__ o4 = (float4*)(out + (size_t)r * (C_ * NBIN)
                                                + (size_t)quad * (CH_Q * NBIN));
        for (int i = tid; i < (CH_Q * NBIN) / 4; i += 256)   // 784 float4s
            o4[i] = s4[i];
    }
}

// ---------------------------------------------------------------------------
extern "C" void kernel_launch(void* const* d_in, const int* in_sizes, int n_in,
                              void* d_out, int out_size) {
    (void)n_in; (void)out_size;
    const float* input = (const float*)d_in[0];
    const float* rois  = (const float*)d_in[1];
    int roi_elems = in_sizes[1];
    if (in_sizes[0] < in_sizes[1]) {          // identify rois by size
        input = (const float*)d_in[1];
        rois  = (const float*)d_in[0];
        roi_elems = in_sizes[0];
    }
    const int R = roi_elems / 6;
    float* out = (float*)d_out;

    nchw_to_nhwc<<<dim3(HW_ / 32, C_ / 128, N_), 256>>>(input);

    const int smem_bytes = NS * 32 + CH_Q * NBIN * 4;  // 18816 B
    cudaFuncSetAttribute(roi_align_rotated,
                         cudaFuncAttributeMaxDynamicSharedMemorySize, smem_bytes);
    const int total_items = R * 4;
    const int grid = (GATHER_GRID < total_items) ? GATHER_GRID : total_items;
    roi_align_rotated<<<grid, 256, smem_bytes>>>(rois, out, total_items);
}

// round 12
// speedup vs baseline: 1.0042x; 1.0042x over previous
#include <cuda_runtime.h>
#include <cuda_fp16.h>

#define N_   2
#define C_   256
#define H_   200
#define W_   304
#define HW_  (H_ * W_)
#define PH_  7
#define PW_  7
#define NBIN 49
#define NS   196          // 49 bins * 4 samples
#define SCALE 0.25f
#define CH_Q   64               // channels per gather block (quarter)
#define GRP    (CH_Q / 4)       // 16 4-channel (uint2) groups per block

// NHWC fp16 scratch (62.3 MB) -> L2-resident on GB300 (126 MB L2).
__device__ __half g_nhwc[(size_t)N_ * HW_ * C_];

// ---------------------------------------------------------------------------
// Kernel 1: NCHW fp32 -> NHWC fp16 for ONE 128-channel group (cbase).
// half2 conversion at load; uint[32][65] smem tile (conflict-free STS);
// STG.128 stores (8 contiguous channels per thread).
// ---------------------------------------------------------------------------
__global__ void __launch_bounds__(256) nchw_to_nhwc(const float* __restrict__ in,
                                                    int cbase) {
    __shared__ unsigned int tile[32 * 65];   // [hw][channel-pair], pad 65
    const int n   = blockIdx.z;
    const int hw0 = blockIdx.x * 32;
    const int c0  = cbase;
    const int t   = threadIdx.x;
    const int w   = t >> 5;     // warp 0..7
    const int l   = t & 31;     // lane = hw offset

    const float* src = in + (size_t)n * C_ * HW_ + (size_t)c0 * HW_ + hw0;
#pragma unroll
    for (int i = 0; i < 8; ++i) {
        const int cp = i * 8 + w;                       // channel pair 0..63
        const float f0 = __ldcs(&src[(size_t)(2 * cp + 0) * HW_ + l]);
        const float f1 = __ldcs(&src[(size_t)(2 * cp + 1) * HW_ + l]);
        const __half2 h = __floats2half2_rn(f0, f1);
        tile[l * 65 + cp] = *reinterpret_cast<const unsigned int*>(&h);
    }
    __syncthreads();

    __half* dst = g_nhwc + (size_t)n * HW_ * C_ + (size_t)hw0 * C_ + c0;
    const int c16 = t & 15;     // 8-channel group (4 uints)
    const int sh  = t >> 4;     // 0..15
#pragma unroll
    for (int pass = 0; pass < 2; ++pass) {
        const int hwr = pass * 16 + sh;
        uint4 v;
        v.x = tile[hwr * 65 + 4 * c16 + 0];
        v.y = tile[hwr * 65 + 4 * c16 + 1];
        v.z = tile[hwr * 65 + 4 * c16 + 2];
        v.w = tile[hwr * 65 + 4 * c16 + 3];
        *reinterpret_cast<uint4*>(dst + (size_t)hwr * C_ + 8 * c16) = v;
    }
}

__device__ __forceinline__ __half2 as_h2(unsigned int v) {
    return *reinterpret_cast<const __half2*>(&v);
}

// ---------------------------------------------------------------------------
// Kernel 2 (R9-validated body): blocks = (roi, 64-ch quarter), qbase selects
// the channel half. 256 threads = 16 channel groups x 16 bin phases.
// Pair-fused HFMA2 chains, 0.25 pre-scaled weights, identity [c][s] staging,
// vector-copy output pass.
// ---------------------------------------------------------------------------
__global__ void __launch_bounds__(256, 8) roi_align_rotated(
    const float* __restrict__ rois, float* __restrict__ out, int qbase) {
    extern __shared__ char smem_raw[];
    int*          s_off = (int*)smem_raw;                    // NS*4 ints    (3136 B)
    unsigned int* s_wh  = (unsigned int*)(smem_raw + NS*16); // NS*4 half2   (3136 B)
    float*        s_out = (float*)(smem_raw + NS * 32);      // 64*49 floats (12544 B)

    const int r    = blockIdx.x >> 1;
    const int quad = (blockIdx.x & 1) + qbase;
    const int tid  = threadIdx.x;

    if (tid < NS) {
        const float* rp = rois + (size_t)r * 6;
        const int   b     = (int)rp[0];
        const float cxr   = fmaf(rp[1], SCALE, -0.5f);
        const float cyr   = fmaf(rp[2], SCALE, -0.5f);
        const float rw    = rp[3] * SCALE;
        const float rh    = rp[4] * SCALE;
        const float theta = rp[5] * 0.017453292519943295f;  // pi/180
        float st, ct;
        sincosf(theta, &st, &ct);

        const float bin_h = rh * (1.0f / PH_);
        const float bin_w = rw * (1.0f / PW_);

        // sample id t = (ph*7+pw)*4 + gy*2 + gx
        const int g  = tid & 3;
        const int s  = tid >> 2;
        const int gy = g >> 1;
        const int gx = g & 1;
        const int ph = s / 7;
        const int pw = s - ph * 7;

        const float yy = -0.5f * rh + (float)ph * bin_h + ((float)gy + 0.5f) * bin_h * 0.5f;
        const float xx = -0.5f * rw + (float)pw * bin_w + ((float)gx + 0.5f) * bin_w * 0.5f;

        const float y = yy * ct - xx * st + cyr;
        const float x = yy * st + xx * ct + cxr;

        const bool valid = (y >= -1.0f) && (y <= (float)H_) &&
                           (x >= -1.0f) && (x <= (float)W_);

        const float yc = fminf(fmaxf(y, 0.0f), (float)(H_ - 1));
        const float xc = fminf(fmaxf(x, 0.0f), (float)(W_ - 1));
        const int   yl = (int)floorf(yc);
        const int   xl = (int)floorf(xc);
        const int   yh = min(yl + 1, H_ - 1);
        const int   xh = min(xl + 1, W_ - 1);
        const float ly = yc - (float)yl;
        const float lx = xc - (float)xl;
        const float hy = 1.0f - ly;
        const float hx = 1.0f - lx;
        // 0.25 mean factor pre-folded into fp16 weights (exact: power of 2)
        const float vf = valid ? 0.25f : 0.0f;

        const int base = b * HW_;
        const int hofs = quad * GRP;       // channel-quarter offset, uint2 units
        s_off[tid * 4 + 0] = (base + yl * W_ + xl) * (C_ / 4) + hofs;
        s_off[tid * 4 + 1] = (base + yl * W_ + xh) * (C_ / 4) + hofs;
        s_off[tid * 4 + 2] = (base + yh * W_ + xl) * (C_ / 4) + hofs;
        s_off[tid * 4 + 3] = (base + yh * W_ + xh) * (C_ / 4) + hofs;
        const __half2 w0 = __float2half2_rn(hy * hx * vf);
        const __half2 w1 = __float2half2_rn(hy * lx * vf);
        const __half2 w2 = __float2half2_rn(ly * hx * vf);
        const __half2 w3 = __float2half2_rn(ly * lx * vf);
        s_wh[tid * 4 + 0] = *reinterpret_cast<const unsigned int*>(&w0);
        s_wh[tid * 4 + 1] = *reinterpret_cast<const unsigned int*>(&w1);
        s_wh[tid * 4 + 2] = *reinterpret_cast<const unsigned int*>(&w2);
        s_wh[tid * 4 + 3] = *reinterpret_cast<const unsigned int*>(&w3);
    }
    __syncthreads();

    const uint2* __restrict__ in2 = (const uint2*)g_nhwc;
    const int cg = tid & (GRP - 1);   // 4-channel group within this quarter
    const int q  = tid >> 4;          // bin phase 0..15

    for (int s = q; s < NBIN; s += 16) {
        const int  t0  = s << 2;
        const int4  oA0 = ((const int4*)s_off)[t0 + 0];
        const int4  oA1 = ((const int4*)s_off)[t0 + 1];
        const int4  oB0 = ((const int4*)s_off)[t0 + 2];
        const int4  oB1 = ((const int4*)s_off)[t0 + 3];
        const uint4 wA0 = ((const uint4*)s_wh)[t0 + 0];
        const uint4 wA1 = ((const uint4*)s_wh)[t0 + 1];
        const uint4 wB0 = ((const uint4*)s_wh)[t0 + 2];
        const uint4 wB1 = ((const uint4*)s_wh)[t0 + 3];

        const uint2 a0 = in2[oA0.x + cg];
        const uint2 a1 = in2[oA0.y + cg];
        const uint2 a2 = in2[oA0.z + cg];
        const uint2 a3 = in2[oA0.w + cg];
        const uint2 a4 = in2[oA1.x + cg];
        const uint2 a5 = in2[oA1.y + cg];
        const uint2 a6 = in2[oA1.z + cg];
        const uint2 a7 = in2[oA1.w + cg];
        const uint2 b0 = in2[oB0.x + cg];
        const uint2 b1 = in2[oB0.y + cg];
        const uint2 b2 = in2[oB0.z + cg];
        const uint2 b3 = in2[oB0.w + cg];
        const uint2 b4 = in2[oB1.x + cg];
        const uint2 b5 = in2[oB1.y + cg];
        const uint2 b6 = in2[oB1.z + cg];
        const uint2 b7 = in2[oB1.w + cg];

        // pair A: fused fp16 chain over 8 corner terms (samples 0,1)
        __half2 h0 = __hmul2(as_h2(a0.x), as_h2(wA0.x));
        __half2 h1 = __hmul2(as_h2(a0.y), as_h2(wA0.x));
        h0 = __hfma2(as_h2(a1.x), as_h2(wA0.y), h0);
        h1 = __hfma2(as_h2(a1.y), as_h2(wA0.y), h1);
        h0 = __hfma2(as_h2(a2.x), as_h2(wA0.z), h0);
        h1 = __hfma2(as_h2(a2.y), as_h2(wA0.z), h1);
        h0 = __hfma2(as_h2(a3.x), as_h2(wA0.w), h0);
        h1 = __hfma2(as_h2(a3.y), as_h2(wA0.w), h1);
        h0 = __hfma2(as_h2(a4.x), as_h2(wA1.x), h0);
        h1 = __hfma2(as_h2(a4.y), as_h2(wA1.x), h1);
        h0 = __hfma2(as_h2(a5.x), as_h2(wA1.y), h0);
        h1 = __hfma2(as_h2(a5.y), as_h2(wA1.y), h1);
        h0 = __hfma2(as_h2(a6.x), as_h2(wA1.z), h0);
        h1 = __hfma2(as_h2(a6.y), as_h2(wA1.z), h1);
        h0 = __hfma2(as_h2(a7.x), as_h2(wA1.w), h0);
        h1 = __hfma2(as_h2(a7.y), as_h2(wA1.w), h1);
        // pair B: independent chain (samples 2,3)
        __half2 g0 = __hmul2(as_h2(b0.x), as_h2(wB0.x));
        __half2 g1 = __hmul2(as_h2(b0.y), as_h2(wB0.x));
        g0 = __hfma2(as_h2(b1.x), as_h2(wB0.y), g0);
        g1 = __hfma2(as_h2(b1.y), as_h2(wB0.y), g1);
        g0 = __hfma2(as_h2(b2.x), as_h2(wB0.z), g0);
        g1 = __hfma2(as_h2(b2.y), as_h2(wB0.z), g1);
        g0 = __hfma2(as_h2(b3.x), as_h2(wB0.w), g0);
        g1 = __hfma2(as_h2(b3.y), as_h2(wB0.w), g1);
        g0 = __hfma2(as_h2(b4.x), as_h2(wB1.x), g0);
        g1 = __hfma2(as_h2(b4.y), as_h2(wB1.x), g1);
        g0 = __hfma2(as_h2(b5.x), as_h2(wB1.y), g0);
        g1 = __hfma2(as_h2(b5.y), as_h2(wB1.y), g1);
        g0 = __hfma2(as_h2(b6.x), as_h2(wB1.z), g0);
        g1 = __hfma2(as_h2(b6.y), as_h2(wB1.z), g1);
        g0 = __hfma2(as_h2(b7.x), as_h2(wB1.w), g0);
        g1 = __hfma2(as_h2(b7.y), as_h2(wB1.w), g1);

        // combine pairs in fp32 (weights carry the 0.25 mean factor)
        const float2 fA0 = __half22float2(h0);
        const float2 fA1 = __half22float2(h1);
        const float2 fB0 = __half22float2(g0);
        const float2 fB1 = __half22float2(g1);
        // identity staging: s_out[c*49 + s]
        s_out[(4 * cg + 0) * NBIN + s] = fA0.x + fB0.x;
        s_out[(4 * cg + 1) * NBIN + s] = fA0.y + fB0.y;
        s_out[(4 * cg + 2) * NBIN + s] = fA1.x + fB1.x;
        s_out[(4 * cg + 3) * NBIN + s] = fA1.y + fB1.y;
    }
    __syncthreads();

    // output pass: pure vector copy, zero index math
    const float4* __restrict__ s4 = (const float4*)s_out;
    float4* __restrict__ o4 = (float4*)(out + (size_t)r * (C_ * NBIN)
                                            + (size_t)quad * (CH_Q * NBIN));
    for (int i = tid; i < (CH_Q * NBIN) / 4; i += 256)   // 784 float4s
        o4[i] = s4[i];
}

// ---------------------------------------------------------------------------
// Overlap with corrected dispatch order:
//   main: T(ch0-127) -> ev1 -> T(ch128-255) -> G(quads 2,3)
//   side:              ev1 -> G(quads 0,1)  -> ev2
//   main: wait ev2
// T2 is enqueued BEFORE G1, so its DRAM-bound blocks dispatch first and G1's
// L1-bound blocks back-fill as they retire -> real overlap (fixes R8).
// ---------------------------------------------------------------------------
static cudaStream_t g_side = nullptr;
static cudaEvent_t  g_ev1 = nullptr, g_ev2 = nullptr;

extern "C" void kernel_launch(void* const* d_in, const int* in_sizes, int n_in,
                              void* d_out, int out_size) {
    (void)n_in; (void)out_size;
    const float* input = (const float*)d_in[0];
    const float* rois  = (const float*)d_in[1];
    int roi_elems = in_sizes[1];
    if (in_sizes[0] < in_sizes[1]) {          // identify rois by size
        input = (const float*)d_in[1];
        rois  = (const float*)d_in[0];
        roi_elems = in_sizes[0];
    }
    const int R = roi_elems / 6;
    float* out = (float*)d_out;

    const int smem_bytes = NS * 32 + CH_Q * NBIN * 4;  // 18816 B
    cudaFuncSetAttribute(roi_align_rotated,
                         cudaFuncAttributeMaxDynamicSharedMemorySize, smem_bytes);

    if (!g_side) {
        cudaStreamCreateWithFlags(&g_side, cudaStreamNonBlocking);
        cudaEventCreateWithFlags(&g_ev1, cudaEventDisableTiming);
        cudaEventCreateWithFlags(&g_ev2, cudaEventDisableTiming);
    }

    const dim3 tgrid(HW_ / 32, 1, N_);   // 3800 blocks per 128-ch half

    if (g_side && g_ev1 && g_ev2) {
        nchw_to_nhwc<<<tgrid, 256>>>(input, 0);                       // T1
        cudaEventRecord(g_ev1, 0);
        nchw_to_nhwc<<<tgrid, 256>>>(input, 128);                     // T2 (enqueued first!)
        cudaStreamWaitEvent(g_side, g_ev1, 0);
        roi_align_rotated<<<R * 2, 256, smem_bytes, g_side>>>(rois, out, 0);  // G1 (needs T1)
        roi_align_rotated<<<R * 2, 256, smem_bytes>>>(rois, out, 2);          // G2 (needs T2)
        cudaEventRecord(g_ev2, g_side);
        cudaStreamWaitEvent(0, g_ev2, 0);
    } else {
        // fallback: sequential on default stream
        nchw_to_nhwc<<<tgrid, 256>>>(input, 0);
        nchw_to_nhwc<<<tgrid, 256>>>(input, 128);
        roi_align_rotated<<<R * 2, 256, smem_bytes>>>(rois, out, 0);
        roi_align_rotated<<<R * 2, 256, smem_bytes>>>(rois, out, 2);
    }
}

// round 13
// speedup vs baseline: 1.0640x; 1.0595x over previous
#include <cuda_runtime.h>
#include <cuda_fp16.h>

#define N_   2
#define C_   256
#define H_   200
#define W_   304
#define HW_  (H_ * W_)
#define PH_  7
#define PW_  7
#define NBIN 49
#define NS   196          // 49 bins * 4 samples
#define SCALE 0.25f
#define CH_Q   64               // channels per gather block (quarter)
#define GRP    (CH_Q / 4)       // 16 4-channel (uint2) groups per block

// NHWC fp16 scratch (62.3 MB) -> L2-resident on GB300 (126 MB L2).
__device__ __half g_nhwc[(size_t)N_ * HW_ * C_];

// ---------------------------------------------------------------------------
// Kernel 1: NCHW fp32 -> NHWC fp16. Tile = 128 channels x 32 hw positions.
// fp32 reads evict-first (__ldcs: used once); NHWC writes default policy
// (they are the image the gather will re-read from L2).
// ---------------------------------------------------------------------------
__global__ void __launch_bounds__(256) nchw_to_nhwc(const float* __restrict__ in) {
    __shared__ unsigned int tile[32 * 65];   // [hw][channel-pair], pad 65
    const int n   = blockIdx.z;
    const int hw0 = blockIdx.x * 32;
    const int c0  = blockIdx.y * 128;
    const int t   = threadIdx.x;
    const int w   = t >> 5;     // warp 0..7
    const int l   = t & 31;     // lane = hw offset

    const float* src = in + (size_t)n * C_ * HW_ + (size_t)c0 * HW_ + hw0;
#pragma unroll
    for (int i = 0; i < 8; ++i) {
        const int cp = i * 8 + w;                       // channel pair 0..63
        const float f0 = __ldcs(&src[(size_t)(2 * cp + 0) * HW_ + l]);
        const float f1 = __ldcs(&src[(size_t)(2 * cp + 1) * HW_ + l]);
        const __half2 h = __floats2half2_rn(f0, f1);
        tile[l * 65 + cp] = *reinterpret_cast<const unsigned int*>(&h);
    }
    __syncthreads();

    __half* dst = g_nhwc + (size_t)n * HW_ * C_ + (size_t)hw0 * C_ + c0;
    const int c16 = t & 15;     // 8-channel group (4 uints)
    const int sh  = t >> 4;     // 0..15
#pragma unroll
    for (int pass = 0; pass < 2; ++pass) {
        const int hwr = pass * 16 + sh;
        uint4 v;
        v.x = tile[hwr * 65 + 4 * c16 + 0];
        v.y = tile[hwr * 65 + 4 * c16 + 1];
        v.z = tile[hwr * 65 + 4 * c16 + 2];
        v.w = tile[hwr * 65 + 4 * c16 + 3];
        *reinterpret_cast<uint4*>(dst + (size_t)hwr * C_ + 8 * c16) = v;
    }
}

__device__ __forceinline__ __half2 as_h2(unsigned int v) {
    return *reinterpret_cast<const __half2*>(&v);
}

// ---------------------------------------------------------------------------
// Kernel 2 (R9 structure): FOUR blocks per ROI (64-ch quarters), grid 4000,
// 8 blocks/SM. 256 threads = 16 channel groups x 16 bin phases. Pair-fused
// HFMA2 chains, 0.25 pre-scaled weights, identity [c][s] staging.
// Output pass uses __stcs (evict-first): the 50 MB output stream no longer
// evicts the 62 MB fp16 image from L2 -> gather reads stay L2-resident.
// ---------------------------------------------------------------------------
__global__ void __launch_bounds__(256, 8) roi_align_rotated(
    const float* __restrict__ rois, float* __restrict__ out) {
    extern __shared__ char smem_raw[];
    int*          s_off = (int*)smem_raw;                    // NS*4 ints    (3136 B)
    unsigned int* s_wh  = (unsigned int*)(smem_raw + NS*16); // NS*4 half2   (3136 B)
    float*        s_out = (float*)(smem_raw + NS * 32);      // 64*49 floats (12544 B)

    const int r    = blockIdx.x >> 2;
    const int quad = blockIdx.x & 3;
    const int tid  = threadIdx.x;

    if (tid < NS) {
        const float* rp = rois + (size_t)r * 6;
        const int   b     = (int)rp[0];
        const float cxr   = fmaf(rp[1], SCALE, -0.5f);
        const float cyr   = fmaf(rp[2], SCALE, -0.5f);
        const float rw    = rp[3] * SCALE;
        const float rh    = rp[4] * SCALE;
        const float theta = rp[5] * 0.017453292519943295f;  // pi/180
        float st, ct;
        sincosf(theta, &st, &ct);

        const float bin_h = rh * (1.0f / PH_);
        const float bin_w = rw * (1.0f / PW_);

        // sample id t = (ph*7+pw)*4 + gy*2 + gx
        const int g  = tid & 3;
        const int s  = tid >> 2;
        const int gy = g >> 1;
        const int gx = g & 1;
        const int ph = s / 7;
        const int pw = s - ph * 7;

        const float yy = -0.5f * rh + (float)ph * bin_h + ((float)gy + 0.5f) * bin_h * 0.5f;
        const float xx = -0.5f * rw + (float)pw * bin_w + ((float)gx + 0.5f) * bin_w * 0.5f;

        const float y = yy * ct - xx * st + cyr;
        const float x = yy * st + xx * ct + cxr;

        const bool valid = (y >= -1.0f) && (y <= (float)H_) &&
                           (x >= -1.0f) && (x <= (float)W_);

        const float yc = fminf(fmaxf(y, 0.0f), (float)(H_ - 1));
        const float xc = fminf(fmaxf(x, 0.0f), (float)(W_ - 1));
        const int   yl = (int)floorf(yc);
        const int   xl = (int)floorf(xc);
        const int   yh = min(yl + 1, H_ - 1);
        const int   xh = min(xl + 1, W_ - 1);
        const float ly = yc - (float)yl;
        const float lx = xc - (float)xl;
        const float hy = 1.0f - ly;
        const float hx = 1.0f - lx;
        // 0.25 mean factor pre-folded into fp16 weights (exact: power of 2)
        const float vf = valid ? 0.25f : 0.0f;

        const int base = b * HW_;
        const int hofs = quad * GRP;       // channel-quarter offset, uint2 units
        s_off[tid * 4 + 0] = (base + yl * W_ + xl) * (C_ / 4) + hofs;
        s_off[tid * 4 + 1] = (base + yl * W_ + xh) * (C_ / 4) + hofs;
        s_off[tid * 4 + 2] = (base + yh * W_ + xl) * (C_ / 4) + hofs;
        s_off[tid * 4 + 3] = (base + yh * W_ + xh) * (C_ / 4) + hofs;
        const __half2 w0 = __float2half2_rn(hy * hx * vf);
        const __half2 w1 = __float2half2_rn(hy * lx * vf);
        const __half2 w2 = __float2half2_rn(ly * hx * vf);
        const __half2 w3 = __float2half2_rn(ly * lx * vf);
        s_wh[tid * 4 + 0] = *reinterpret_cast<const unsigned int*>(&w0);
        s_wh[tid * 4 + 1] = *reinterpret_cast<const unsigned int*>(&w1);
        s_wh[tid * 4 + 2] = *reinterpret_cast<const unsigned int*>(&w2);
        s_wh[tid * 4 + 3] = *reinterpret_cast<const unsigned int*>(&w3);
    }
    __syncthreads();

    const uint2* __restrict__ in2 = (const uint2*)g_nhwc;
    const int cg = tid & (GRP - 1);   // 4-channel group within this quarter
    const int q  = tid >> 4;          // bin phase 0..15

    for (int s = q; s < NBIN; s += 16) {
        const int  t0  = s << 2;
        const int4  oA0 = ((const int4*)s_off)[t0 + 0];
        const int4  oA1 = ((const int4*)s_off)[t0 + 1];
        const int4  oB0 = ((const int4*)s_off)[t0 + 2];
        const int4  oB1 = ((const int4*)s_off)[t0 + 3];
        const uint4 wA0 = ((const uint4*)s_wh)[t0 + 0];
        const uint4 wA1 = ((const uint4*)s_wh)[t0 + 1];
        const uint4 wB0 = ((const uint4*)s_wh)[t0 + 2];
        const uint4 wB1 = ((const uint4*)s_wh)[t0 + 3];

        const uint2 a0 = in2[oA0.x + cg];
        const uint2 a1 = in2[oA0.y + cg];
        const uint2 a2 = in2[oA0.z + cg];
        const uint2 a3 = in2[oA0.w + cg];
        const uint2 a4 = in2[oA1.x + cg];
        const uint2 a5 = in2[oA1.y + cg];
        const uint2 a6 = in2[oA1.z + cg];
        const uint2 a7 = in2[oA1.w + cg];
        const uint2 b0 = in2[oB0.x + cg];
        const uint2 b1 = in2[oB0.y + cg];
        const uint2 b2 = in2[oB0.z + cg];
        const uint2 b3 = in2[oB0.w + cg];
        const uint2 b4 = in2[oB1.x + cg];
        const uint2 b5 = in2[oB1.y + cg];
        const uint2 b6 = in2[oB1.z + cg];
        const uint2 b7 = in2[oB1.w + cg];

        // pair A: fused fp16 chain over 8 corner terms (samples 0,1)
        __half2 h0 = __hmul2(as_h2(a0.x), as_h2(wA0.x));
        __half2 h1 = __hmul2(as_h2(a0.y), as_h2(wA0.x));
        h0 = __hfma2(as_h2(a1.x), as_h2(wA0.y), h0);
        h1 = __hfma2(as_h2(a1.y), as_h2(wA0.y), h1);
        h0 = __hfma2(as_h2(a2.x), as_h2(wA0.z), h0);
        h1 = __hfma2(as_h2(a2.y), as_h2(wA0.z), h1);
        h0 = __hfma2(as_h2(a3.x), as_h2(wA0.w), h0);
        h1 = __hfma2(as_h2(a3.y), as_h2(wA0.w), h1);
        h0 = __hfma2(as_h2(a4.x), as_h2(wA1.x), h0);
        h1 = __hfma2(as_h2(a4.y), as_h2(wA1.x), h1);
        h0 = __hfma2(as_h2(a5.x), as_h2(wA1.y), h0);
        h1 = __hfma2(as_h2(a5.y), as_h2(wA1.y), h1);
        h0 = __hfma2(as_h2(a6.x), as_h2(wA1.z), h0);
        h1 = __hfma2(as_h2(a6.y), as_h2(wA1.z), h1);
        h0 = __hfma2(as_h2(a7.x), as_h2(wA1.w), h0);
        h1 = __hfma2(as_h2(a7.y), as_h2(wA1.w), h1);
        // pair B: independent chain (samples 2,3)
        __half2 g0 = __hmul2(as_h2(b0.x), as_h2(wB0.x));
        __half2 g1 = __hmul2(as_h2(b0.y), as_h2(wB0.x));
        g0 = __hfma2(as_h2(b1.x), as_h2(wB0.y), g0);
        g1 = __hfma2(as_h2(b1.y), as_h2(wB0.y), g1);
        g0 = __hfma2(as_h2(b2.x), as_h2(wB0.z), g0);
        g1 = __hfma2(as_h2(b2.y), as_h2(wB0.z), g1);
        g0 = __hfma2(as_h2(b3.x), as_h2(wB0.w), g0);
        g1 = __hfma2(as_h2(b3.y), as_h2(wB0.w), g1);
        g0 = __hfma2(as_h2(b4.x), as_h2(wB1.x), g0);
        g1 = __hfma2(as_h2(b4.y), as_h2(wB1.x), g1);
        g0 = __hfma2(as_h2(b5.x), as_h2(wB1.y), g0);
        g1 = __hfma2(as_h2(b5.y), as_h2(wB1.y), g1);
        g0 = __hfma2(as_h2(b6.x), as_h2(wB1.z), g0);
        g1 = __hfma2(as_h2(b6.y), as_h2(wB1.z), g1);
        g0 = __hfma2(as_h2(b7.x), as_h2(wB1.w), g0);
        g1 = __hfma2(as_h2(b7.y), as_h2(wB1.w), g1);

        // combine pairs in fp32 (weights carry the 0.25 mean factor)
        const float2 fA0 = __half22float2(h0);
        const float2 fA1 = __half22float2(h1);
        const float2 fB0 = __half22float2(g0);
        const float2 fB1 = __half22float2(g1);
        // identity staging: s_out[c*49 + s]
        s_out[(4 * cg + 0) * NBIN + s] = fA0.x + fB0.x;
        s_out[(4 * cg + 1) * NBIN + s] = fA0.y + fB0.y;
        s_out[(4 * cg + 2) * NBIN + s] = fA1.x + fB1.x;
        s_out[(4 * cg + 3) * NBIN + s] = fA1.y + fB1.y;
    }
    __syncthreads();

    // output pass: vector copy with streaming stores (evict-first) so the
    // 50 MB output doesn't evict the fp16 image from L2.
    const float4* __restrict__ s4 = (const float4*)s_out;
    float4* __restrict__ o4 = (float4*)(out + (size_t)r * (C_ * NBIN)
                                            + (size_t)quad * (CH_Q * NBIN));
    for (int i = tid; i < (CH_Q * NBIN) / 4; i += 256)   // 784 float4s
        __stcs(&o4[i], s4[i]);
}

// ---------------------------------------------------------------------------
extern "C" void kernel_launch(void* const* d_in, const int* in_sizes, int n_in,
                              void* d_out, int out_size) {
    (void)n_in; (void)out_size;
    const float* input = (const float*)d_in[0];
    const float* rois  = (const float*)d_in[1];
    int roi_elems = in_sizes[1];
    if (in_sizes[0] < in_sizes[1]) {          // identify rois by size
        input = (const float*)d_in[1];
        rois  = (const float*)d_in[0];
        roi_elems = in_sizes[0];
    }
    const int R = roi_elems / 6;
    float* out = (float*)d_out;

    nchw_to_nhwc<<<dim3(HW_ / 32, C_ / 128, N_), 256>>>(input);

    const int smem_bytes = NS * 32 + CH_Q * NBIN * 4;  // 18816 B
    cudaFuncSetAttribute(roi_align_rotated,
                         cudaFuncAttributeMaxDynamicSharedMemorySize, smem_bytes);
    roi_align_rotated<<<R * 4, 256, smem_bytes>>>(rois, out);
}

// round 14
// speedup vs baseline: 1.0830x; 1.0178x over previous
#include <cuda_runtime.h>
#include <cuda_fp16.h>

#define N_   2
#define C_   256
#define H_   200
#define W_   304
#define HW_  (H_ * W_)
#define PH_  7
#define PW_  7
#define NBIN 49
#define NS   196          // 49 bins * 4 samples
#define SCALE 0.25f
#define CH_Q   64               // channels per gather block (quarter)
#define GRP    (CH_Q / 4)       // 16 4-channel (uint2) groups per block

// NHWC fp16 scratch (62.3 MB) -> L2-resident on GB300 (126 MB L2).
__device__ __half g_nhwc[(size_t)N_ * HW_ * C_];

// ---------------------------------------------------------------------------
// Kernel 1: NCHW fp32 -> NHWC fp16. Tile = 128 channels x 32 hw positions.
// fp32 reads evict-first (__ldcs: used once); NHWC writes default policy
// (they are the image the gather will re-read from L2).
// ---------------------------------------------------------------------------
__global__ void __launch_bounds__(256) nchw_to_nhwc(const float* __restrict__ in) {
    __shared__ unsigned int tile[32 * 65];   // [hw][channel-pair], pad 65
    const int n   = blockIdx.z;
    const int hw0 = blockIdx.x * 32;
    const int c0  = blockIdx.y * 128;
    const int t   = threadIdx.x;
    const int w   = t >> 5;     // warp 0..7
    const int l   = t & 31;     // lane = hw offset

    const float* src = in + (size_t)n * C_ * HW_ + (size_t)c0 * HW_ + hw0;
#pragma unroll
    for (int i = 0; i < 8; ++i) {
        const int cp = i * 8 + w;                       // channel pair 0..63
        const float f0 = __ldcs(&src[(size_t)(2 * cp + 0) * HW_ + l]);
        const float f1 = __ldcs(&src[(size_t)(2 * cp + 1) * HW_ + l]);
        const __half2 h = __floats2half2_rn(f0, f1);
        tile[l * 65 + cp] = *reinterpret_cast<const unsigned int*>(&h);
    }
    __syncthreads();

    __half* dst = g_nhwc + (size_t)n * HW_ * C_ + (size_t)hw0 * C_ + c0;
    const int c16 = t & 15;     // 8-channel group (4 uints)
    const int sh  = t >> 4;     // 0..15
#pragma unroll
    for (int pass = 0; pass < 2; ++pass) {
        const int hwr = pass * 16 + sh;
        uint4 v;
        v.x = tile[hwr * 65 + 4 * c16 + 0];
        v.y = tile[hwr * 65 + 4 * c16 + 1];
        v.z = tile[hwr * 65 + 4 * c16 + 2];
        v.w = tile[hwr * 65 + 4 * c16 + 3];
        *reinterpret_cast<uint4*>(dst + (size_t)hwr * C_ + 8 * c16) = v;
    }
}

__device__ __forceinline__ __half2 as_h2(unsigned int v) {
    return *reinterpret_cast<const __half2*>(&v);
}

// ---------------------------------------------------------------------------
// Kernel 2: FOUR blocks per ROI (64-ch quarters), grid 4000.
// __launch_bounds__(256,6): 42-reg budget so ptxas can keep the full 16-load
// batch in flight (MLP ~16) instead of serializing under the 32-reg cap.
// 256 threads = 16 channel groups x 16 bin phases. Pair-fused HFMA2 chains,
// 0.25 pre-scaled weights, identity [c][s] staging, __stcs streaming output.
// ---------------------------------------------------------------------------
__global__ void __launch_bounds__(256, 6) roi_align_rotated(
    const float* __restrict__ rois, float* __restrict__ out) {
    extern __shared__ char smem_raw[];
    int*          s_off = (int*)smem_raw;                    // NS*4 ints    (3136 B)
    unsigned int* s_wh  = (unsigned int*)(smem_raw + NS*16); // NS*4 half2   (3136 B)
    float*        s_out = (float*)(smem_raw + NS * 32);      // 64*49 floats (12544 B)

    const int r    = blockIdx.x >> 2;
    const int quad = blockIdx.x & 3;
    const int tid  = threadIdx.x;

    if (tid < NS) {
        const float* rp = rois + (size_t)r * 6;
        const int   b     = (int)rp[0];
        const float cxr   = fmaf(rp[1], SCALE, -0.5f);
        const float cyr   = fmaf(rp[2], SCALE, -0.5f);
        const float rw    = rp[3] * SCALE;
        const float rh    = rp[4] * SCALE;
        const float theta = rp[5] * 0.017453292519943295f;  // pi/180
        float st, ct;
        sincosf(theta, &st, &ct);

        const float bin_h = rh * (1.0f / PH_);
        const float bin_w = rw * (1.0f / PW_);

        // sample id t = (ph*7+pw)*4 + gy*2 + gx
        const int g  = tid & 3;
        const int s  = tid >> 2;
        const int gy = g >> 1;
        const int gx = g & 1;
        const int ph = s / 7;
        const int pw = s - ph * 7;

        const float yy = -0.5f * rh + (float)ph * bin_h + ((float)gy + 0.5f) * bin_h * 0.5f;
        const float xx = -0.5f * rw + (float)pw * bin_w + ((float)gx + 0.5f) * bin_w * 0.5f;

        const float y = yy * ct - xx * st + cyr;
        const float x = yy * st + xx * ct + cxr;

        const bool valid = (y >= -1.0f) && (y <= (float)H_) &&
                           (x >= -1.0f) && (x <= (float)W_);

        const float yc = fminf(fmaxf(y, 0.0f), (float)(H_ - 1));
        const float xc = fminf(fmaxf(x, 0.0f), (float)(W_ - 1));
        const int   yl = (int)floorf(yc);
        const int   xl = (int)floorf(xc);
        const int   yh = min(yl + 1, H_ - 1);
        const int   xh = min(xl + 1, W_ - 1);
        const float ly = yc - (float)yl;
        const float lx = xc - (float)xl;
        const float hy = 1.0f - ly;
        const float hx = 1.0f - lx;
        // 0.25 mean factor pre-folded into fp16 weights (exact: power of 2)
        const float vf = valid ? 0.25f : 0.0f;

        const int base = b * HW_;
        const int hofs = quad * GRP;       // channel-quarter offset, uint2 units
        s_off[tid * 4 + 0] = (base + yl * W_ + xl) * (C_ / 4) + hofs;
        s_off[tid * 4 + 1] = (base + yl * W_ + xh) * (C_ / 4) + hofs;
        s_off[tid * 4 + 2] = (base + yh * W_ + xl) * (C_ / 4) + hofs;
        s_off[tid * 4 + 3] = (base + yh * W_ + xh) * (C_ / 4) + hofs;
        const __half2 w0 = __float2half2_rn(hy * hx * vf);
        const __half2 w1 = __float2half2_rn(hy * lx * vf);
        const __half2 w2 = __float2half2_rn(ly * hx * vf);
        const __half2 w3 = __float2half2_rn(ly * lx * vf);
        s_wh[tid * 4 + 0] = *reinterpret_cast<const unsigned int*>(&w0);
        s_wh[tid * 4 + 1] = *reinterpret_cast<const unsigned int*>(&w1);
        s_wh[tid * 4 + 2] = *reinterpret_cast<const unsigned int*>(&w2);
        s_wh[tid * 4 + 3] = *reinterpret_cast<const unsigned int*>(&w3);
    }
    __syncthreads();

    const uint2* __restrict__ in2 = (const uint2*)g_nhwc;
    const int cg = tid & (GRP - 1);   // 4-channel group within this quarter
    const int q  = tid >> 4;          // bin phase 0..15

    for (int s = q; s < NBIN; s += 16) {
        const int  t0  = s << 2;
        const int4  oA0 = ((const int4*)s_off)[t0 + 0];
        const int4  oA1 = ((const int4*)s_off)[t0 + 1];
        const int4  oB0 = ((const int4*)s_off)[t0 + 2];
        const int4  oB1 = ((const int4*)s_off)[t0 + 3];
        const uint4 wA0 = ((const uint4*)s_wh)[t0 + 0];
        const uint4 wA1 = ((const uint4*)s_wh)[t0 + 1];
        const uint4 wB0 = ((const uint4*)s_wh)[t0 + 2];
        const uint4 wB1 = ((const uint4*)s_wh)[t0 + 3];

        const uint2 a0 = in2[oA0.x + cg];
        const uint2 a1 = in2[oA0.y + cg];
        const uint2 a2 = in2[oA0.z + cg];
        const uint2 a3 = in2[oA0.w + cg];
        const uint2 a4 = in2[oA1.x + cg];
        const uint2 a5 = in2[oA1.y + cg];
        const uint2 a6 = in2[oA1.z + cg];
        const uint2 a7 = in2[oA1.w + cg];
        const uint2 b0 = in2[oB0.x + cg];
        const uint2 b1 = in2[oB0.y + cg];
        const uint2 b2 = in2[oB0.z + cg];
        const uint2 b3 = in2[oB0.w + cg];
        const uint2 b4 = in2[oB1.x + cg];
        const uint2 b5 = in2[oB1.y + cg];
        const uint2 b6 = in2[oB1.z + cg];
        const uint2 b7 = in2[oB1.w + cg];

        // pair A: fused fp16 chain over 8 corner terms (samples 0,1)
        __half2 h0 = __hmul2(as_h2(a0.x), as_h2(wA0.x));
        __half2 h1 = __hmul2(as_h2(a0.y), as_h2(wA0.x));
        h0 = __hfma2(as_h2(a1.x), as_h2(wA0.y), h0);
        h1 = __hfma2(as_h2(a1.y), as_h2(wA0.y), h1);
        h0 = __hfma2(as_h2(a2.x), as_h2(wA0.z), h0);
        h1 = __hfma2(as_h2(a2.y), as_h2(wA0.z), h1);
        h0 = __hfma2(as_h2(a3.x), as_h2(wA0.w), h0);
        h1 = __hfma2(as_h2(a3.y), as_h2(wA0.w), h1);
        h0 = __hfma2(as_h2(a4.x), as_h2(wA1.x), h0);
        h1 = __hfma2(as_h2(a4.y), as_h2(wA1.x), h1);
        h0 = __hfma2(as_h2(a5.x), as_h2(wA1.y), h0);
        h1 = __hfma2(as_h2(a5.y), as_h2(wA1.y), h1);
        h0 = __hfma2(as_h2(a6.x), as_h2(wA1.z), h0);
        h1 = __hfma2(as_h2(a6.y), as_h2(wA1.z), h1);
        h0 = __hfma2(as_h2(a7.x), as_h2(wA1.w), h0);
        h1 = __hfma2(as_h2(a7.y), as_h2(wA1.w), h1);
        // pair B: independent chain (samples 2,3)
        __half2 g0 = __hmul2(as_h2(b0.x), as_h2(wB0.x));
        __half2 g1 = __hmul2(as_h2(b0.y), as_h2(wB0.x));
        g0 = __hfma2(as_h2(b1.x), as_h2(wB0.y), g0);
        g1 = __hfma2(as_h2(b1.y), as_h2(wB0.y), g1);
        g0 = __hfma2(as_h2(b2.x), as_h2(wB0.z), g0);
        g1 = __hfma2(as_h2(b2.y), as_h2(wB0.z), g1);
        g0 = __hfma2(as_h2(b3.x), as_h2(wB0.w), g0);
        g1 = __hfma2(as_h2(b3.y), as_h2(wB0.w), g1);
        g0 = __hfma2(as_h2(b4.x), as_h2(wB1.x), g0);
        g1 = __hfma2(as_h2(b4.y), as_h2(wB1.x), g1);
        g0 = __hfma2(as_h2(b5.x), as_h2(wB1.y), g0);
        g1 = __hfma2(as_h2(b5.y), as_h2(wB1.y), g1);
        g0 = __hfma2(as_h2(b6.x), as_h2(wB1.z), g0);
        g1 = __hfma2(as_h2(b6.y), as_h2(wB1.z), g1);
        g0 = __hfma2(as_h2(b7.x), as_h2(wB1.w), g0);
        g1 = __hfma2(as_h2(b7.y), as_h2(wB1.w), g1);

        // combine pairs in fp32 (weights carry the 0.25 mean factor)
        const float2 fA0 = __half22float2(h0);
        const float2 fA1 = __half22float2(h1);
        const float2 fB0 = __half22float2(g0);
        const float2 fB1 = __half22float2(g1);
        // identity staging: s_out[c*49 + s]
        s_out[(4 * cg + 0) * NBIN + s] = fA0.x + fB0.x;
        s_out[(4 * cg + 1) * NBIN + s] = fA0.y + fB0.y;
        s_out[(4 * cg + 2) * NBIN + s] = fA1.x + fB1.x;
        s_out[(4 * cg + 3) * NBIN + s] = fA1.y + fB1.y;
    }
    __syncthreads();

    // output pass: vector copy with streaming stores (evict-first) so the
    // 50 MB output doesn't evict the fp16 image from L2.
    const float4* __restrict__ s4 = (const float4*)s_out;
    float4* __restrict__ o4 = (float4*)(out + (size_t)r * (C_ * NBIN)
                                            + (size_t)quad * (CH_Q * NBIN));
    for (int i = tid; i < (CH_Q * NBIN) / 4; i += 256)   // 784 float4s
        __stcs(&o4[i], s4[i]);
}

// ---------------------------------------------------------------------------
extern "C" void kernel_launch(void* const* d_in, const int* in_sizes, int n_in,
                              void* d_out, int out_size) {
    (void)n_in; (void)out_size;
    const float* input = (const float*)d_in[0];
    const float* rois  = (const float*)d_in[1];
    int roi_elems = in_sizes[1];
    if (in_sizes[0] < in_sizes[1]) {          // identify rois by size
        input = (const float*)d_in[1];
        rois  = (const float*)d_in[0];
        roi_elems = in_sizes[0];
    }
    const int R = roi_elems / 6;
    float* out = (float*)d_out;

    nchw_to_nhwc<<<dim3(HW_ / 32, C_ / 128, N_), 256>>>(input);

    const int smem_bytes = NS * 32 + CH_Q * NBIN * 4;  // 18816 B
    cudaFuncSetAttribute(roi_align_rotated,
                         cudaFuncAttributeMaxDynamicSharedMemorySize, smem_bytes);
    roi_align_rotated<<<R * 4, 256, smem_bytes>>>(rois, out);
}

// round 15
// speedup vs baseline: 1.0952x; 1.0113x over previous
#include <cuda_runtime.h>
#include <cuda_fp16.h>

#define N_   2
#define C_   256
#define H_   200
#define W_   304
#define HW_  (H_ * W_)
#define PH_  7
#define PW_  7
#define NBIN 49
#define NS   196          // 49 bins * 4 samples
#define SCALE 0.25f
#define CH_Q   64               // channels per gather block (quarter)
#define GRP    (CH_Q / 4)       // 16 4-channel (uint2) groups per block

// NHWC fp16 scratch (62.3 MB) -> L2-resident on GB300 (126 MB L2).
__device__ __half g_nhwc[(size_t)N_ * HW_ * C_];

// ---------------------------------------------------------------------------
// Kernel 1: NCHW fp32 -> NHWC fp16. Tile = 128 channels x 32 hw positions.
// fp32 reads evict-first (__ldcs: used once); NHWC writes default policy
// (they are the image the gather will re-read from L2).
// ---------------------------------------------------------------------------
__global__ void __launch_bounds__(256) nchw_to_nhwc(const float* __restrict__ in) {
    __shared__ unsigned int tile[32 * 65];   // [hw][channel-pair], pad 65
    const int n   = blockIdx.z;
    const int hw0 = blockIdx.x * 32;
    const int c0  = blockIdx.y * 128;
    const int t   = threadIdx.x;
    const int w   = t >> 5;     // warp 0..7
    const int l   = t & 31;     // lane = hw offset

    const float* src = in + (size_t)n * C_ * HW_ + (size_t)c0 * HW_ + hw0;
#pragma unroll
    for (int i = 0; i < 8; ++i) {
        const int cp = i * 8 + w;                       // channel pair 0..63
        const float f0 = __ldcs(&src[(size_t)(2 * cp + 0) * HW_ + l]);
        const float f1 = __ldcs(&src[(size_t)(2 * cp + 1) * HW_ + l]);
        const __half2 h = __floats2half2_rn(f0, f1);
        tile[l * 65 + cp] = *reinterpret_cast<const unsigned int*>(&h);
    }
    __syncthreads();

    __half* dst = g_nhwc + (size_t)n * HW_ * C_ + (size_t)hw0 * C_ + c0;
    const int c16 = t & 15;     // 8-channel group (4 uints)
    const int sh  = t >> 4;     // 0..15
#pragma unroll
    for (int pass = 0; pass < 2; ++pass) {
        const int hwr = pass * 16 + sh;
        uint4 v;
        v.x = tile[hwr * 65 + 4 * c16 + 0];
        v.y = tile[hwr * 65 + 4 * c16 + 1];
        v.z = tile[hwr * 65 + 4 * c16 + 2];
        v.w = tile[hwr * 65 + 4 * c16 + 3];
        *reinterpret_cast<uint4*>(dst + (size_t)hwr * C_ + 8 * c16) = v;
    }
}

__device__ __forceinline__ __half2 as_h2(unsigned int v) {
    return *reinterpret_cast<const __half2*>(&v);
}

// ---------------------------------------------------------------------------
// Kernel 2: FOUR blocks per ROI (64-ch quarters), grid 4000.
// __launch_bounds__(256,5): 51-reg budget so ptxas can keep the FULL 16-load
// batch in flight (R13->R14 showed 32->40 regs bought 2 us; batch still split).
// 256 threads = 16 channel groups x 16 bin phases. Pair-fused HFMA2 chains,
// 0.25 pre-scaled weights, identity [c][s] staging, __stcs streaming output.
// ---------------------------------------------------------------------------
__global__ void __launch_bounds__(256, 5) roi_align_rotated(
    const float* __restrict__ rois, float* __restrict__ out) {
    extern __shared__ char smem_raw[];
    int*          s_off = (int*)smem_raw;                    // NS*4 ints    (3136 B)
    unsigned int* s_wh  = (unsigned int*)(smem_raw + NS*16); // NS*4 half2   (3136 B)
    float*        s_out = (float*)(smem_raw + NS * 32);      // 64*49 floats (12544 B)

    const int r    = blockIdx.x >> 2;
    const int quad = blockIdx.x & 3;
    const int tid  = threadIdx.x;

    if (tid < NS) {
        const float* rp = rois + (size_t)r * 6;
        const int   b     = (int)rp[0];
        const float cxr   = fmaf(rp[1], SCALE, -0.5f);
        const float cyr   = fmaf(rp[2], SCALE, -0.5f);
        const float rw    = rp[3] * SCALE;
        const float rh    = rp[4] * SCALE;
        const float theta = rp[5] * 0.017453292519943295f;  // pi/180
        float st, ct;
        sincosf(theta, &st, &ct);

        const float bin_h = rh * (1.0f / PH_);
        const float bin_w = rw * (1.0f / PW_);

        // sample id t = (ph*7+pw)*4 + gy*2 + gx
        const int g  = tid & 3;
        const int s  = tid >> 2;
        const int gy = g >> 1;
        const int gx = g & 1;
        const int ph = s / 7;
        const int pw = s - ph * 7;

        const float yy = -0.5f * rh + (float)ph * bin_h + ((float)gy + 0.5f) * bin_h * 0.5f;
        const float xx = -0.5f * rw + (float)pw * bin_w + ((float)gx + 0.5f) * bin_w * 0.5f;

        const float y = yy * ct - xx * st + cyr;
        const float x = yy * st + xx * ct + cxr;

        const bool valid = (y >= -1.0f) && (y <= (float)H_) &&
                           (x >= -1.0f) && (x <= (float)W_);

        const float yc = fminf(fmaxf(y, 0.0f), (float)(H_ - 1));
        const float xc = fminf(fmaxf(x, 0.0f), (float)(W_ - 1));
        const int   yl = (int)floorf(yc);
        const int   xl = (int)floorf(xc);
        const int   yh = min(yl + 1, H_ - 1);
        const int   xh = min(xl + 1, W_ - 1);
        const float ly = yc - (float)yl;
        const float lx = xc - (float)xl;
        const float hy = 1.0f - ly;
        const float hx = 1.0f - lx;
        // 0.25 mean factor pre-folded into fp16 weights (exact: power of 2)
        const float vf = valid ? 0.25f : 0.0f;

        const int base = b * HW_;
        const int hofs = quad * GRP;       // channel-quarter offset, uint2 units
        s_off[tid * 4 + 0] = (base + yl * W_ + xl) * (C_ / 4) + hofs;
        s_off[tid * 4 + 1] = (base + yl * W_ + xh) * (C_ / 4) + hofs;
        s_off[tid * 4 + 2] = (base + yh * W_ + xl) * (C_ / 4) + hofs;
        s_off[tid * 4 + 3] = (base + yh * W_ + xh) * (C_ / 4) + hofs;
        const __half2 w0 = __float2half2_rn(hy * hx * vf);
        const __half2 w1 = __float2half2_rn(hy * lx * vf);
        const __half2 w2 = __float2half2_rn(ly * hx * vf);
        const __half2 w3 = __float2half2_rn(ly * lx * vf);
        s_wh[tid * 4 + 0] = *reinterpret_cast<const unsigned int*>(&w0);
        s_wh[tid * 4 + 1] = *reinterpret_cast<const unsigned int*>(&w1);
        s_wh[tid * 4 + 2] = *reinterpret_cast<const unsigned int*>(&w2);
        s_wh[tid * 4 + 3] = *reinterpret_cast<const unsigned int*>(&w3);
    }
    __syncthreads();

    const uint2* __restrict__ in2 = (const uint2*)g_nhwc;
    const int cg = tid & (GRP - 1);   // 4-channel group within this quarter
    const int q  = tid >> 4;          // bin phase 0..15

    for (int s = q; s < NBIN; s += 16) {
        const int  t0  = s << 2;
        const int4  oA0 = ((const int4*)s_off)[t0 + 0];
        const int4  oA1 = ((const int4*)s_off)[t0 + 1];
        const int4  oB0 = ((const int4*)s_off)[t0 + 2];
        const int4  oB1 = ((const int4*)s_off)[t0 + 3];
        const uint4 wA0 = ((const uint4*)s_wh)[t0 + 0];
        const uint4 wA1 = ((const uint4*)s_wh)[t0 + 1];
        const uint4 wB0 = ((const uint4*)s_wh)[t0 + 2];
        const uint4 wB1 = ((const uint4*)s_wh)[t0 + 3];

        const uint2 a0 = in2[oA0.x + cg];
        const uint2 a1 = in2[oA0.y + cg];
        const uint2 a2 = in2[oA0.z + cg];
        const uint2 a3 = in2[oA0.w + cg];
        const uint2 a4 = in2[oA1.x + cg];
        const uint2 a5 = in2[oA1.y + cg];
        const uint2 a6 = in2[oA1.z + cg];
        const uint2 a7 = in2[oA1.w + cg];
        const uint2 b0 = in2[oB0.x + cg];
        const uint2 b1 = in2[oB0.y + cg];
        const uint2 b2 = in2[oB0.z + cg];
        const uint2 b3 = in2[oB0.w + cg];
        const uint2 b4 = in2[oB1.x + cg];
        const uint2 b5 = in2[oB1.y + cg];
        const uint2 b6 = in2[oB1.z + cg];
        const uint2 b7 = in2[oB1.w + cg];

        // pair A: fused fp16 chain over 8 corner terms (samples 0,1)
        __half2 h0 = __hmul2(as_h2(a0.x), as_h2(wA0.x));
        __half2 h1 = __hmul2(as_h2(a0.y), as_h2(wA0.x));
        h0 = __hfma2(as_h2(a1.x), as_h2(wA0.y), h0);
        h1 = __hfma2(as_h2(a1.y), as_h2(wA0.y), h1);
        h0 = __hfma2(as_h2(a2.x), as_h2(wA0.z), h0);
        h1 = __hfma2(as_h2(a2.y), as_h2(wA0.z), h1);
        h0 = __hfma2(as_h2(a3.x), as_h2(wA0.w), h0);
        h1 = __hfma2(as_h2(a3.y), as_h2(wA0.w), h1);
        h0 = __hfma2(as_h2(a4.x), as_h2(wA1.x), h0);
        h1 = __hfma2(as_h2(a4.y), as_h2(wA1.x), h1);
        h0 = __hfma2(as_h2(a5.x), as_h2(wA1.y), h0);
        h1 = __hfma2(as_h2(a5.y), as_h2(wA1.y), h1);
        h0 = __hfma2(as_h2(a6.x), as_h2(wA1.z), h0);
        h1 = __hfma2(as_h2(a6.y), as_h2(wA1.z), h1);
        h0 = __hfma2(as_h2(a7.x), as_h2(wA1.w), h0);
        h1 = __hfma2(as_h2(a7.y), as_h2(wA1.w), h1);
        // pair B: independent chain (samples 2,3)
        __half2 g0 = __hmul2(as_h2(b0.x), as_h2(wB0.x));
        __half2 g1 = __hmul2(as_h2(b0.y), as_h2(wB0.x));
        g0 = __hfma2(as_h2(b1.x), as_h2(wB0.y), g0);
        g1 = __hfma2(as_h2(b1.y), as_h2(wB0.y), g1);
        g0 = __hfma2(as_h2(b2.x), as_h2(wB0.z), g0);
        g1 = __hfma2(as_h2(b2.y), as_h2(wB0.z), g1);
        g0 = __hfma2(as_h2(b3.x), as_h2(wB0.w), g0);
        g1 = __hfma2(as_h2(b3.y), as_h2(wB0.w), g1);
        g0 = __hfma2(as_h2(b4.x), as_h2(wB1.x), g0);
        g1 = __hfma2(as_h2(b4.y), as_h2(wB1.x), g1);
        g0 = __hfma2(as_h2(b5.x), as_h2(wB1.y), g0);
        g1 = __hfma2(as_h2(b5.y), as_h2(wB1.y), g1);
        g0 = __hfma2(as_h2(b6.x), as_h2(wB1.z), g0);
        g1 = __hfma2(as_h2(b6.y), as_h2(wB1.z), g1);
        g0 = __hfma2(as_h2(b7.x), as_h2(wB1.w), g0);
        g1 = __hfma2(as_h2(b7.y), as_h2(wB1.w), g1);

        // combine pairs in fp32 (weights carry the 0.25 mean factor)
        const float2 fA0 = __half22float2(h0);
        const float2 fA1 = __half22float2(h1);
        const float2 fB0 = __half22float2(g0);
        const float2 fB1 = __half22float2(g1);
        // identity staging: s_out[c*49 + s]
        s_out[(4 * cg + 0) * NBIN + s] = fA0.x + fB0.x;
        s_out[(4 * cg + 1) * NBIN + s] = fA0.y + fB0.y;
        s_out[(4 * cg + 2) * NBIN + s] = fA1.x + fB1.x;
        s_out[(4 * cg + 3) * NBIN + s] = fA1.y + fB1.y;
    }
    __syncthreads();

    // output pass: vector copy with streaming stores (evict-first) so the
    // 50 MB output doesn't evict the fp16 image from L2.
    const float4* __restrict__ s4 = (const float4*)s_out;
    float4* __restrict__ o4 = (float4*)(out + (size_t)r * (C_ * NBIN)
                                            + (size_t)quad * (CH_Q * NBIN));
    for (int i = tid; i < (CH_Q * NBIN) / 4; i += 256)   // 784 float4s
        __stcs(&o4[i], s4[i]);
}

// ---------------------------------------------------------------------------
extern "C" void kernel_launch(void* const* d_in, const int* in_sizes, int n_in,
                              void* d_out, int out_size) {
    (void)n_in; (void)out_size;
    const float* input = (const float*)d_in[0];
    const float* rois  = (const float*)d_in[1];
    int roi_elems = in_sizes[1];
    if (in_sizes[0] < in_sizes[1]) {          // identify rois by size
        input = (const float*)d_in[1];
        rois  = (const float*)d_in[0];
        roi_elems = in_sizes[0];
    }
    const int R = roi_elems / 6;
    float* out = (float*)d_out;

    nchw_to_nhwc<<<dim3(HW_ / 32, C_ / 128, N_), 256>>>(input);

    const int smem_bytes = NS * 32 + CH_Q * NBIN * 4;  // 18816 B
    cudaFuncSetAttribute(roi_align_rotated,
                         cudaFuncAttributeMaxDynamicSharedMemorySize, smem_bytes);
    roi_align_rotated<<<R * 4, 256, smem_bytes>>>(rois, out);
}